// round 14
// baseline (speedup 1.0000x reference)
#include <cuda_runtime.h>
#include <cstdint>

// BilinearInteraction: out[b, p, :] = x[b, i_p, :] * (x[b, j_p, :] @ W)
//   x: [4096, 32, 64] f32, W: [64, 64] f32, out: [4096, 496, 64] f32
//   R10 per-CTA profile at 448 threads / 4 CTAs/SM:
//   - 592 concurrent CTAs -> 6.92 waves (tail ~1% vs 8% at 256x6)
//   - GEMM on warps 0-7 only (LSU layout + 32-reg compile preserved)
//   - write phase on 14 warps, near-perfect balance: rows (w, 27-w) = 35
//     pairs each; rows 28/29/30 appended to warps 13/12/11 (max 38)
//   - W via cp.async.bulk; padded xs; row-sequential stcs streams

#define NF 32
#define ED 64
#define NP 496
#define NTHREADS 448
#define NBATCH 4096
#define XSTR 17                   // xs row stride in float4

__device__ __forceinline__ unsigned smem_u32(const void* p) {
    unsigned a;
    asm("{ .reg .u64 t; cvta.to.shared.u64 t, %1; cvt.u32.u64 %0, t; }"
        : "=r"(a) : "l"(p));
    return a;
}

__global__ void __launch_bounds__(NTHREADS, 4)
bilinear_kernel(const float* __restrict__ x,
                const float* __restrict__ W,
                float* __restrict__ out)
{
    __shared__ float4 xs4[NF * XSTR];            // 8704 B (padded)
    __shared__ float4 vs4[NF * (ED / 4)];        // 8192 B
    __shared__ float4 Ws4[ED * (ED / 4)];        // 16384 B
    __shared__ __align__(8) unsigned long long mbar;

    const int b   = blockIdx.x;
    const int tid = threadIdx.x;

    // ---- mbarrier init, then W via 1D bulk copy (async proxy) ----
    if (tid == 0) {
        asm volatile("mbarrier.init.shared.b64 [%0], 1;"
                     :: "r"(smem_u32(&mbar)) : "memory");
    }
    __syncthreads();
    if (tid == 0) {
        const unsigned mb = smem_u32(&mbar);
        asm volatile("mbarrier.arrive.expect_tx.shared.b64 _, [%0], %1;"
                     :: "r"(mb), "r"(16384u) : "memory");
        asm volatile(
            "cp.async.bulk.shared::cluster.global.mbarrier::complete_tx::bytes "
            "[%0], [%1], %2, [%3];"
            :: "r"(smem_u32(Ws4)), "l"(W), "r"(16384u), "r"(mb) : "memory");
    }

    // ---- x prologue: padded copy (512 f4 over 448 threads) ----
    {
        const float4* xg = (const float4*)(x + (size_t)b * (NF * ED));
        {
            const int idx = tid;
            xs4[(idx >> 4) * XSTR + (idx & 15)] = xg[idx];
        }
        if (tid < 64) {
            const int idx = 448 + tid;
            xs4[(idx >> 4) * XSTR + (idx & 15)] = xg[idx];
        }
    }
    __syncthreads();

    // ---- wait for W (acquire) ----
    {
        const unsigned mb = smem_u32(&mbar);
        unsigned done;
        asm volatile(
            "{\n\t.reg .pred p;\n\t"
            "mbarrier.try_wait.parity.acquire.cta.shared::cta.b64 p, [%1], 0;\n\t"
            "selp.b32 %0, 1, 0, p;\n\t}"
            : "=r"(done) : "r"(mb) : "memory");
        while (!done) {
            asm volatile(
                "{\n\t.reg .pred p;\n\t"
                "mbarrier.try_wait.parity.acquire.cta.shared::cta.b64 p, [%1], 0, 0x989680;\n\t"
                "selp.b32 %0, 1, 0, p;\n\t}"
                : "=r"(done) : "r"(mb) : "memory");
        }
    }

    const int w    = tid >> 5;        // 0..13
    const int lane = tid & 31;

    // ---- GEMM on warps 0-7 (exact R10/R13 layout) ----
    // Warp w: wr = w&3 (rows 8wr..8wr+7), half = w>>2 (e-f4 cols 8h..8h+7).
    // Lane: fi = lane>>3 (row), ci = lane&7 (col). Rows f0, f0+4; col c.
    if (w < 8) {
        const int wr   = w & 3;
        const int half = w >> 2;
        const int fi   = lane >> 3;
        const int ci   = lane & 7;
        const int f0   = 8 * wr + fi;
        const int c    = 8 * half + ci;

        float4 acc0 = make_float4(0.f, 0.f, 0.f, 0.f);
        float4 acc1 = make_float4(0.f, 0.f, 0.f, 0.f);

#pragma unroll 4
        for (int d4 = 0; d4 < 16; d4++) {
            const float4 xv0 = xs4[f0 * XSTR + d4];
            const float4 xv1 = xs4[(f0 + 4) * XSTR + d4];
#pragma unroll
            for (int dd = 0; dd < 4; dd++) {
                const float4 wv = Ws4[(4 * d4 + dd) * 16 + c];
                const float xa = (dd == 0) ? xv0.x : (dd == 1) ? xv0.y :
                                 (dd == 2) ? xv0.z : xv0.w;
                const float xb = (dd == 0) ? xv1.x : (dd == 1) ? xv1.y :
                                 (dd == 2) ? xv1.z : xv1.w;
                acc0.x = fmaf(xa, wv.x, acc0.x);
                acc0.y = fmaf(xa, wv.y, acc0.y);
                acc0.z = fmaf(xa, wv.z, acc0.z);
                acc0.w = fmaf(xa, wv.w, acc0.w);
                acc1.x = fmaf(xb, wv.x, acc1.x);
                acc1.y = fmaf(xb, wv.y, acc1.y);
                acc1.z = fmaf(xb, wv.z, acc1.z);
                acc1.w = fmaf(xb, wv.w, acc1.w);
            }
        }
        vs4[f0 * 16 + c]       = acc0;
        vs4[(f0 + 4) * 16 + c] = acc1;
    }
    __syncthreads();

    // ---- Write phase: 14 warps, balanced row-sequential streams ----
    // Warp w: rows {w, 27-w} = (31-w) + (4+w) = 35 pairs.
    // Extra: w13 += row 28 (3), w12 += row 29 (2), w11 += row 30 (1).
    {
        const int v = lane & 15;
        const int h = lane >> 4;

        float4* out4 = (float4*)(out + (size_t)b * (NP * ED));

        int rows[3];
        int nrows = 2;
        rows[0] = w;
        rows[1] = 27 - w;
        rows[2] = 0;
        if (w == 13) { rows[2] = 28; nrows = 3; }
        else if (w == 12) { rows[2] = 29; nrows = 3; }
        else if (w == 11) { rows[2] = 30; nrows = 3; }

#pragma unroll
        for (int r = 0; r < 3; r++) {
            if (r >= nrows) break;
            const int i = rows[r];
            const float4 a  = xs4[i * XSTR + v];
            const int cnt   = 31 - i;
            const int iters = (cnt + 1 - h) >> 1;   // exact per half-lane
            const int p0    = (i * (63 - i)) >> 1;

#pragma unroll 2
            for (int t = 0; t < iters; t++) {
                const int j = i + 1 + 2 * t + h;
                const float4 cvv = vs4[j * 16 + v];
                const int p = p0 + (j - i - 1);
                float4 rr;
                rr.x = a.x * cvv.x;
                rr.y = a.y * cvv.y;
                rr.z = a.z * cvv.z;
                rr.w = a.w * cvv.w;
                __stcs(out4 + p * 16 + v, rr);
            }
        }
    }
}

extern "C" void kernel_launch(void* const* d_in, const int* in_sizes, int n_in,
                              void* d_out, int out_size)
{
    const float* x = (const float*)d_in[0];
    const float* W = (const float*)d_in[1];
    float*       o = (float*)d_out;
    bilinear_kernel<<<NBATCH, NTHREADS>>>(x, W, o);
}

// round 15
// speedup vs baseline: 1.0791x; 1.0791x over previous
#include <cuda_runtime.h>
#include <cstdint>

// BilinearInteraction: out[b, p, :] = x[b, i_p, :] * (x[b, j_p, :] @ W)
//   x: [4096, 32, 64] f32, W: [64, 64] f32, out: [4096, 496, 64] f32
//   R10 frame (champion) + perfectly balanced write phase:
//   warp w owns rows {2w, 31-2w, 2w+1, 30-2w} = exactly 62 pairs/warp
//   (triangle identity: rows i and 31-i total 31 pairs; 2 units per warp).
//   - grid 4096, 256 threads, 6 CTAs/SM
//   - W via cp.async.bulk; padded xs; LSU-optimal GEMM; stcs stores

#define NF 32
#define ED 64
#define NP 496
#define NTHREADS 256
#define NBATCH 4096
#define XSTR 17                   // xs row stride in float4

__device__ __forceinline__ unsigned smem_u32(const void* p) {
    unsigned a;
    asm("{ .reg .u64 t; cvta.to.shared.u64 t, %1; cvt.u32.u64 %0, t; }"
        : "=r"(a) : "l"(p));
    return a;
}

__global__ void __launch_bounds__(NTHREADS, 6)
bilinear_kernel(const float* __restrict__ x,
                const float* __restrict__ W,
                float* __restrict__ out)
{
    __shared__ float4 xs4[NF * XSTR];            // 8704 B (padded)
    __shared__ float4 vs4[NF * (ED / 4)];        // 8192 B
    __shared__ float4 Ws4[ED * (ED / 4)];        // 16384 B
    __shared__ __align__(8) unsigned long long mbar;

    const int b   = blockIdx.x;
    const int tid = threadIdx.x;

    // ---- mbarrier init, then W via 1D bulk copy (async proxy) ----
    if (tid == 0) {
        asm volatile("mbarrier.init.shared.b64 [%0], 1;"
                     :: "r"(smem_u32(&mbar)) : "memory");
    }
    __syncthreads();
    if (tid == 0) {
        const unsigned mb = smem_u32(&mbar);
        asm volatile("mbarrier.arrive.expect_tx.shared.b64 _, [%0], %1;"
                     :: "r"(mb), "r"(16384u) : "memory");
        asm volatile(
            "cp.async.bulk.shared::cluster.global.mbarrier::complete_tx::bytes "
            "[%0], [%1], %2, [%3];"
            :: "r"(smem_u32(Ws4)), "l"(W), "r"(16384u), "r"(mb) : "memory");
    }

    // ---- x prologue: padded copy ----
    {
        const float4* xg = (const float4*)(x + (size_t)b * (NF * ED));
#pragma unroll
        for (int k = 0; k < 2; k++) {
            const int idx = tid + k * NTHREADS;   // 0..511
            const int row = idx >> 4;
            const int col = idx & 15;
            xs4[row * XSTR + col] = xg[idx];
        }
    }
    __syncthreads();

    // ---- wait for W (acquire) ----
    {
        const unsigned mb = smem_u32(&mbar);
        unsigned done;
        asm volatile(
            "{\n\t.reg .pred p;\n\t"
            "mbarrier.try_wait.parity.acquire.cta.shared::cta.b64 p, [%1], 0;\n\t"
            "selp.b32 %0, 1, 0, p;\n\t}"
            : "=r"(done) : "r"(mb) : "memory");
        while (!done) {
            asm volatile(
                "{\n\t.reg .pred p;\n\t"
                "mbarrier.try_wait.parity.acquire.cta.shared::cta.b64 p, [%1], 0, 0x989680;\n\t"
                "selp.b32 %0, 1, 0, p;\n\t}"
                : "=r"(done) : "r"(mb) : "memory");
        }
    }

    // ---- GEMM: vid[f][e] = sum_d x[f][d] * W[d][e] (R10, LSU-optimal) ----
    // Warp w: wr = w&3 (rows 8wr..8wr+7), half = w>>2 (e-f4 cols 8h..8h+7).
    // Lane: fi = lane>>3 (row), ci = lane&7 (col). Rows f0, f0+4; col c.
    {
        const int w    = tid >> 5;
        const int lane = tid & 31;
        const int wr   = w & 3;
        const int half = w >> 2;
        const int fi   = lane >> 3;
        const int ci   = lane & 7;
        const int f0   = 8 * wr + fi;
        const int c    = 8 * half + ci;

        float4 acc0 = make_float4(0.f, 0.f, 0.f, 0.f);
        float4 acc1 = make_float4(0.f, 0.f, 0.f, 0.f);

#pragma unroll 4
        for (int d4 = 0; d4 < 16; d4++) {
            const float4 xv0 = xs4[f0 * XSTR + d4];
            const float4 xv1 = xs4[(f0 + 4) * XSTR + d4];
#pragma unroll
            for (int dd = 0; dd < 4; dd++) {
                const float4 wv = Ws4[(4 * d4 + dd) * 16 + c];
                const float xa = (dd == 0) ? xv0.x : (dd == 1) ? xv0.y :
                                 (dd == 2) ? xv0.z : xv0.w;
                const float xb = (dd == 0) ? xv1.x : (dd == 1) ? xv1.y :
                                 (dd == 2) ? xv1.z : xv1.w;
                acc0.x = fmaf(xa, wv.x, acc0.x);
                acc0.y = fmaf(xa, wv.y, acc0.y);
                acc0.z = fmaf(xa, wv.z, acc0.z);
                acc0.w = fmaf(xa, wv.w, acc0.w);
                acc1.x = fmaf(xb, wv.x, acc1.x);
                acc1.y = fmaf(xb, wv.y, acc1.y);
                acc1.z = fmaf(xb, wv.z, acc1.z);
                acc1.w = fmaf(xb, wv.w, acc1.w);
            }
        }
        vs4[f0 * 16 + c]       = acc0;
        vs4[(f0 + 4) * 16 + c] = acc1;
    }
    __syncthreads();

    // ---- Write phase: perfectly balanced row-sequential streams ----
    // Warp w: rows {2w, 31-2w, 2w+1, 30-2w} = (31-2w)+2w+(30-2w)+(2w+1)
    // = 62 pairs for every warp. (w=0: row 31 contributes 0 pairs.)
    {
        const int w    = tid >> 5;
        const int lane = tid & 31;
        const int v    = lane & 15;
        const int h    = lane >> 4;

        float4* out4 = (float4*)(out + (size_t)b * (NP * ED));

        const int rows[4] = { 2 * w, 31 - 2 * w, 2 * w + 1, 30 - 2 * w };

#pragma unroll
        for (int r = 0; r < 4; r++) {
            const int i = rows[r];
            const float4 a  = xs4[i * XSTR + v];
            const int cnt   = 31 - i;                 // 0 for the w=0 row 31
            const int iters = (cnt + 1 - h) >> 1;     // exact per half-lane
            const int p0    = (i * (63 - i)) >> 1;

#pragma unroll 2
            for (int t = 0; t < iters; t++) {
                const int j = i + 1 + 2 * t + h;
                const float4 cvv = vs4[j * 16 + v];
                const int p = p0 + (j - i - 1);
                float4 rr;
                rr.x = a.x * cvv.x;
                rr.y = a.y * cvv.y;
                rr.z = a.z * cvv.z;
                rr.w = a.w * cvv.w;
                __stcs(out4 + p * 16 + v, rr);
            }
        }
    }
}

extern "C" void kernel_launch(void* const* d_in, const int* in_sizes, int n_in,
                              void* d_out, int out_size)
{
    const float* x = (const float*)d_in[0];
    const float* W = (const float*)d_in[1];
    float*       o = (float*)d_out;
    bilinear_kernel<<<NBATCH, NTHREADS>>>(x, W, o);
}